// round 3
// baseline (speedup 1.0000x reference)
#include <cuda_runtime.h>
#include <cuda_bf16.h>

// Problem constants (fixed for this problem instance)
#define BDIM   16
#define DDIM   256
#define TDIM   4096
#define NTOK   (BDIM * TDIM)   // 65536
#define NEMB   1024
#define NBOOKS 8

#define NEG_INF (-3.0e38f)

// Scratch: residual (N, D) row-major, and per-embedding 0.5*||e||^2
__device__ float g_resid[NTOK * DDIM];          // 64 MB
__device__ float g_cn[NBOOKS * NEMB];

// ---------------- packed f32x2 helpers (Blackwell FFMA2 path) ----------------
__device__ __forceinline__ unsigned long long pk2(float x, float y) {
    unsigned long long r;
    asm("mov.b64 %0, {%1, %2};" : "=l"(r) : "f"(x), "f"(y));
    return r;
}
__device__ __forceinline__ float2 upk2(unsigned long long v) {
    float2 r;
    asm("mov.b64 {%0, %1}, %2;" : "=f"(r.x), "=f"(r.y) : "l"(v));
    return r;
}
#define FFMA2(acc, a, b) asm("fma.rn.f32x2 %0, %1, %2, %0;" : "+l"(acc) : "l"(a), "l"(b))

// Swizzled K-major shared layout: row k holds 128 values; XOR swizzle in
// 16B granules keeps LDS.128 alignment while spreading column writes
// across 8 bank groups (4-way worst-case STS conflict on the fill, which
// is negligible vs. the FMA mainloop).
__device__ __forceinline__ int swz(int k, int c) {
    return k * 128 + (c ^ ((k & 7) << 2));
}

// ---------------- init: residual[n][d] = z[b][d][t], n = b*T + t ----------------
__global__ void init_resid(const float* __restrict__ z) {
    __shared__ float tile[32][33];
    const int b  = blockIdx.z;
    const int d0 = blockIdx.y * 32;
    const int t0 = blockIdx.x * 32;
    const int tx = threadIdx.x, ty = threadIdx.y;
#pragma unroll
    for (int j = 0; j < 32; j += 8)
        tile[ty + j][tx] = z[(b * DDIM + d0 + ty + j) * TDIM + t0 + tx];
    __syncthreads();
#pragma unroll
    for (int j = 0; j < 32; j += 8)
        g_resid[(b * TDIM + t0 + ty + j) * DDIM + d0 + tx] = tile[tx][ty + j];
}

// ---------------- final: out[b][d][t] = z[b][d][t] - residual[n][d] ----------------
__global__ void write_out(const float* __restrict__ z, float* __restrict__ out) {
    __shared__ float tile[32][33];
    const int b  = blockIdx.z;
    const int d0 = blockIdx.y * 32;
    const int t0 = blockIdx.x * 32;
    const int tx = threadIdx.x, ty = threadIdx.y;
#pragma unroll
    for (int j = 0; j < 32; j += 8)
        tile[ty + j][tx] = g_resid[(b * TDIM + t0 + ty + j) * DDIM + d0 + tx];
    __syncthreads();
#pragma unroll
    for (int j = 0; j < 32; j += 8) {
        int zi = (b * DDIM + d0 + ty + j) * TDIM + t0 + tx;
        out[zi] = z[zi] - tile[tx][ty + j];
    }
}

// ---------------- per-embedding half squared norms ----------------
__global__ void norms_kernel(const float* __restrict__ books) {
    const int row  = blockIdx.x * 8 + (threadIdx.x >> 5);   // 8192 rows total
    const int lane = threadIdx.x & 31;
    const float* e = books + row * DDIM;
    float s = 0.f;
#pragma unroll
    for (int i = 0; i < 8; i++) {
        float v = e[lane + i * 32];
        s = fmaf(v, v, s);
    }
#pragma unroll
    for (int off = 16; off; off >>= 1) s += __shfl_xor_sync(0xffffffffu, s, off);
    if (lane == 0) g_cn[row] = 0.5f * s;
}

// ---------------- fused VQ step: GEMM + argmax + residual update ----------------
// Block: 256 threads, tile 128 tokens x (all 1024 embeds in 8 tiles of 128), K=256.
// Thread tile: 8 tokens x 8 embeds, accumulated as 32 f32x2 (token pairs).
__global__ void __launch_bounds__(256) vq_step(const float* __restrict__ books,
                                               const int* __restrict__ nbu,
                                               int book) {
    if (book >= *nbu) return;

    extern __shared__ float sm[];
    float* sA     = sm;                        // 256 x 128 (K-major tokens, swizzled)
    float* sB     = sm + 256 * 128;            // 32 x 128 (K-major embeds, swizzled)
    float* sBestV = sB + 32 * 128;             // 128
    int*   sBestI = (int*)(sBestV + 128);      // 128

    const int tid  = threadIdx.x;
    const int tx   = tid & 15;                 // embed group
    const int ty   = tid >> 4;                 // token group
    const int tok0 = blockIdx.x * 128;
    const float* __restrict__ eb  = books + book * (NEMB * DDIM);
    const float* __restrict__ cnb = g_cn + book * NEMB;

    // Stage the 128-token residual tile: coalesced float4 global reads,
    // transposed swizzled STS.
    {
        const float4* r4 = (const float4*)(g_resid + tok0 * DDIM);
#pragma unroll 4
        for (int u = 0; u < 32; u++) {
            int i = tid + u * 256;
            int t = i >> 6, k4 = i & 63;
            float4 v = r4[t * 64 + k4];
            int k = k4 * 4;
            sA[swz(k, t)]     = v.x;
            sA[swz(k + 1, t)] = v.y;
            sA[swz(k + 2, t)] = v.z;
            sA[swz(k + 3, t)] = v.w;
        }
    }
    if (tid < 128) sBestV[tid] = NEG_INF;
    __syncthreads();

    for (int nt = 0; nt < 8; nt++) {
        const int eBase = nt * 128;

        unsigned long long acc[4][8];
#pragma unroll
        for (int p = 0; p < 4; p++)
#pragma unroll
            for (int e = 0; e < 8; e++) acc[p][e] = 0ull;

        // register prefetch of embedding k-tile 0
        float4 pf[4];
#pragma unroll
        for (int u = 0; u < 4; u++) {
            int i = tid + u * 256;
            int e = i >> 3, k4 = i & 7;
            pf[u] = *(const float4*)(eb + (eBase + e) * DDIM + k4 * 4);
        }

        for (int kt = 0; kt < 256; kt += 32) {
            // commit prefetched tile to shared
#pragma unroll
            for (int u = 0; u < 4; u++) {
                int i = tid + u * 256;
                int e = i >> 3, k = (i & 7) * 4;
                sB[swz(k, e)]     = pf[u].x;
                sB[swz(k + 1, e)] = pf[u].y;
                sB[swz(k + 2, e)] = pf[u].z;
                sB[swz(k + 3, e)] = pf[u].w;
            }
            __syncthreads();
            // prefetch next k-tile while computing this one
            if (kt + 32 < 256) {
#pragma unroll
                for (int u = 0; u < 4; u++) {
                    int i = tid + u * 256;
                    int e = i >> 3, k4 = i & 7;
                    pf[u] = *(const float4*)(eb + (eBase + e) * DDIM + kt + 32 + k4 * 4);
                }
            }

#pragma unroll 8
            for (int kk = 0; kk < 32; kk++) {
                const int kA = kt + kk;
                float4 a0 = *(const float4*)&sA[swz(kA, ty * 8)];
                float4 a1 = *(const float4*)&sA[swz(kA, ty * 8 + 4)];
                float4 b0 = *(const float4*)&sB[swz(kk, tx * 8)];
                float4 b1 = *(const float4*)&sB[swz(kk, tx * 8 + 4)];

                unsigned long long A[4], Bv[8];
                A[0] = pk2(a0.x, a0.y);  A[1] = pk2(a0.z, a0.w);
                A[2] = pk2(a1.x, a1.y);  A[3] = pk2(a1.z, a1.w);
                Bv[0] = pk2(b0.x, b0.x); Bv[1] = pk2(b0.y, b0.y);
                Bv[2] = pk2(b0.z, b0.z); Bv[3] = pk2(b0.w, b0.w);
                Bv[4] = pk2(b1.x, b1.x); Bv[5] = pk2(b1.y, b1.y);
                Bv[6] = pk2(b1.z, b1.z); Bv[7] = pk2(b1.w, b1.w);
#pragma unroll
                for (int p = 0; p < 4; p++)
#pragma unroll
                    for (int e = 0; e < 8; e++)
                        FFMA2(acc[p][e], A[p], Bv[e]);
            }
            __syncthreads();
        }

        // Epilogue: per-token argmax over this 128-embed tile.
        // Tie-break: lowest index wins (matches jnp.argmax first-max).
#pragma unroll
        for (int p = 0; p < 4; p++) {
            float2 sv[8];
#pragma unroll
            for (int e = 0; e < 8; e++) sv[e] = upk2(acc[p][e]);
#pragma unroll
            for (int lane = 0; lane < 2; lane++) {
                float best = NEG_INF;
                int   bidx = 0;
#pragma unroll
                for (int e = 0; e < 8; e++) {
                    int eg = eBase + tx * 8 + e;
                    float s = (lane ? sv[e].y : sv[e].x) - cnb[eg];
                    if (s > best) { best = s; bidx = eg; }   // strict -> earliest kept
                }
                // reduce across the 16 embed-group threads (same tokens)
#pragma unroll
                for (int off = 8; off; off >>= 1) {
                    float ov = __shfl_xor_sync(0xffffffffu, best, off, 16);
                    int   oi = __shfl_xor_sync(0xffffffffu, bidx, off, 16);
                    if (ov > best || (ov == best && oi < bidx)) { best = ov; bidx = oi; }
                }
                if (tx == 0) {
                    int t = ty * 8 + p * 2 + lane;
                    if (best > sBestV[t]) { sBestV[t] = best; sBestI[t] = bidx; }
                }
            }
        }
        // no sync needed here: sBestV/I entries have unique owners, and sB is
        // protected by the syncthreads inside the k-tile loop of the next nt.
    }
    __syncthreads();

    // Gather winning codewords and update residual in place (coalesced;
    // codebook gathers hit L2 — 1 MB/book is resident).
#pragma unroll 4
    for (int u = 0; u < 32; u++) {
        int i  = tid + u * 256;
        int t  = i >> 6, d4 = i & 63;
        int idx = sBestI[t];
        const float4 q = *(const float4*)(eb + idx * DDIM + d4 * 4);
        float4* rp = (float4*)(g_resid + (tok0 + t) * DDIM) + d4;
        float4 r = *rp;
        r.x -= q.x; r.y -= q.y; r.z -= q.z; r.w -= q.w;
        *rp = r;
    }
}

// ---------------- launch ----------------
#define VQ_SMEM ((256 * 128 + 32 * 128 + 128) * 4 + 128 * 4)   // 148480 bytes

extern "C" void kernel_launch(void* const* d_in, const int* in_sizes, int n_in,
                              void* d_out, int out_size) {
    const float* z     = (const float*)d_in[0];
    const float* books = (const float*)d_in[1];
    const int*   nbu   = (const int*)d_in[2];
    float*       out   = (float*)d_out;

    cudaFuncSetAttribute(vq_step, cudaFuncAttributeMaxDynamicSharedMemorySize, VQ_SMEM);

    dim3 tgrid(TDIM / 32, DDIM / 32, BDIM);
    dim3 tblk(32, 8);

    init_resid<<<tgrid, tblk>>>(z);
    norms_kernel<<<(NBOOKS * NEMB) / 8, 256>>>(books);
    for (int k = 0; k < NBOOKS; k++)
        vq_step<<<NTOK / 128, 256, VQ_SMEM>>>(books, nbu, k);
    write_out<<<tgrid, tblk>>>(z, out);
}

// round 7
// speedup vs baseline: 1.1377x; 1.1377x over previous
#include <cuda_runtime.h>
#include <cuda_bf16.h>
#include <cstdint>

// Problem constants
#define BDIM   16
#define DDIM   256
#define TDIM   4096
#define NTOK   (BDIM * TDIM)   // 65536
#define NEMB   1024
#define NBOOKS 8

#define NEG_INF (-3.0e38f)
#define DELTA   1.0e-3f        // uncertainty margin >> worst-case split error

// Scratch
__device__ float g_resid[NTOK * DDIM];                  // 64 MB residual (N, D)
__device__ float g_cn[NBOOKS * NEMB];                   // 0.5*||e||^2
// Pre-split bf16 codebooks, plain row-major [book][emb][k=256]
__device__ __nv_bfloat16 g_bh[NBOOKS * NEMB * DDIM];    // 4 MB
__device__ __nv_bfloat16 g_bl[NBOOKS * NEMB * DDIM];    // 4 MB

// ---------------------------------------------------------------------------
// helpers
// ---------------------------------------------------------------------------
__device__ __forceinline__ uint32_t smem_u32(const void* p) {
    uint32_t a;
    asm("{ .reg .u64 t; cvta.to.shared.u64 t, %1; cvt.u32.u64 %0, t; }" : "=r"(a) : "l"(p));
    return a;
}

#define LDSM4(r, addr)                                                         \
    asm volatile("ldmatrix.sync.aligned.m8n8.x4.shared.b16 {%0,%1,%2,%3}, [%4];" \
        : "=r"((r)[0]), "=r"((r)[1]), "=r"((r)[2]), "=r"((r)[3]) : "r"(addr))

#define MMA_BF16(d, a, b0, b1)                                                 \
    asm volatile("mma.sync.aligned.m16n8k16.row.col.f32.bf16.bf16.f32 "        \
        "{%0,%1,%2,%3}, {%4,%5,%6,%7}, {%8,%9}, {%0,%1,%2,%3};"                \
        : "+f"((d)[0]), "+f"((d)[1]), "+f"((d)[2]), "+f"((d)[3])               \
        : "r"((a)[0]), "r"((a)[1]), "r"((a)[2]), "r"((a)[3]), "r"(b0), "r"(b1))

#define CP16(dst, src) asm volatile("cp.async.cg.shared.global [%0], [%1], 16;" :: "r"(dst), "l"(src))
#define CP_COMMIT()    asm volatile("cp.async.commit_group;" ::: "memory")
#define CP_WAIT1()     asm volatile("cp.async.wait_group 1;" ::: "memory")
#define CP_WAIT0()     asm volatile("cp.async.wait_group 0;" ::: "memory")

// bf16 hi/lo split of a float pair, packed low-first (consecutive k)
__device__ __forceinline__ void splitpack(float a, float b, uint32_t& hi, uint32_t& lo) {
    __nv_bfloat16 ah = __float2bfloat16(a), bh = __float2bfloat16(b);
    __nv_bfloat16 al = __float2bfloat16(a - __bfloat162float(ah));
    __nv_bfloat16 bl = __float2bfloat16(b - __bfloat162float(bh));
    __nv_bfloat162 h2; h2.x = ah; h2.y = bh;
    __nv_bfloat162 l2; l2.x = al; l2.y = bl;
    hi = *reinterpret_cast<uint32_t*>(&h2);
    lo = *reinterpret_cast<uint32_t*>(&l2);
}

__device__ __forceinline__ void top2_merge(float& v1, int& i1, float& v2,
                                           float ov1, int oi1, float ov2) {
    if (ov1 > v1) { v2 = fmaxf(v1, ov2); v1 = ov1; i1 = oi1; }
    else          { v2 = fmaxf(v2, ov1); }
}

// ---------------------------------------------------------------------------
// transpose init / finish kernels (proven in R3)
// ---------------------------------------------------------------------------
__global__ void init_resid(const float* __restrict__ z) {
    __shared__ float tile[32][33];
    const int b = blockIdx.z, d0 = blockIdx.y * 32, t0 = blockIdx.x * 32;
    const int tx = threadIdx.x, ty = threadIdx.y;
#pragma unroll
    for (int j = 0; j < 32; j += 8)
        tile[ty + j][tx] = z[(b * DDIM + d0 + ty + j) * TDIM + t0 + tx];
    __syncthreads();
#pragma unroll
    for (int j = 0; j < 32; j += 8)
        g_resid[(b * TDIM + t0 + ty + j) * DDIM + d0 + tx] = tile[tx][ty + j];
}

__global__ void write_out(const float* __restrict__ z, float* __restrict__ out) {
    __shared__ float tile[32][33];
    const int b = blockIdx.z, d0 = blockIdx.y * 32, t0 = blockIdx.x * 32;
    const int tx = threadIdx.x, ty = threadIdx.y;
#pragma unroll
    for (int j = 0; j < 32; j += 8)
        tile[ty + j][tx] = g_resid[(b * TDIM + t0 + ty + j) * DDIM + d0 + tx];
    __syncthreads();
#pragma unroll
    for (int j = 0; j < 32; j += 8) {
        int zi = (b * DDIM + d0 + ty + j) * TDIM + t0 + tx;
        out[zi] = z[zi] - tile[tx][ty + j];
    }
}

// per-embedding half squared norms + bf16 hi/lo split (1 warp = 1 embed row)
__global__ void prep_books(const float* __restrict__ books) {
    const int row  = blockIdx.x * 8 + (threadIdx.x >> 5);   // 0..8191
    const int lane = threadIdx.x & 31;
    const float4* er4 = (const float4*)(books + (size_t)row * DDIM);
    float4 v0 = er4[lane * 2];
    float4 v1 = er4[lane * 2 + 1];
    float s = v0.x*v0.x + v0.y*v0.y + v0.z*v0.z + v0.w*v0.w
            + v1.x*v1.x + v1.y*v1.y + v1.z*v1.z + v1.w*v1.w;
#pragma unroll
    for (int off = 16; off; off >>= 1) s += __shfl_xor_sync(0xffffffffu, s, off);
    if (lane == 0) g_cn[row] = 0.5f * s;

    uint4 H, L;
    splitpack(v0.x, v0.y, H.x, L.x);
    splitpack(v0.z, v0.w, H.y, L.y);
    splitpack(v1.x, v1.y, H.z, L.z);
    splitpack(v1.z, v1.w, H.w, L.w);
    *(uint4*)(g_bh + (size_t)row * DDIM + lane * 8) = H;
    *(uint4*)(g_bl + (size_t)row * DDIM + lane * 8) = L;
}

// ---------------------------------------------------------------------------
// Fused VQ step on mma.sync (HMMA): 3-term bf16-split GEMM + argmax + fallback
// 256 threads = 8 warps (4 token-rows x 2 embed-cols). CTA: 128 tok x 128 emb.
// ---------------------------------------------------------------------------
// smem byte layout.  A: 4 k-chunks of [128 rows][8 x 16B granules, swizzled]
#define OFF_AH   0                 // 64 KB
#define OFF_AL   65536             // 64 KB
#define OFF_B    131072            // 2 bufs x (hi 16KB + lo 16KB)
#define OFF_CN   196608            // 128 f
#define OFF_V1   197120            // 256 f
#define OFF_V2   198144            // 256 f
#define OFF_I1   199168            // 256 i
#define OFF_BI   200192            // 128 i
#define OFF_UNC  200704            // 4 + 128 i
#define OFF_SR   201232            // 256 f
#define OFF_RV   202256            // 256 f
#define OFF_RI   203280            // 256 i
#define SMEM_TC  204416

__device__ __forceinline__ void copy_b_chunk(uint32_t sbase, int book, int nt,
                                             int kc, int buf, int tid) {
    const __nv_bfloat16* srcH = g_bh + ((size_t)(book * NEMB + nt * 128) * DDIM + kc * 64);
    const __nv_bfloat16* srcL = g_bl + ((size_t)(book * NEMB + nt * 128) * DDIM + kc * 64);
#pragma unroll
    for (int u = 0; u < 4; u++) {
        int idx = tid + u * 256;          // 1024 granules: 128 rows x 8
        int r = idx >> 3, g = idx & 7;
        uint32_t dst = sbase + OFF_B + buf * 32768 + r * 128 + ((g ^ (r & 7)) << 4);
        CP16(dst,         srcH + (size_t)r * DDIM + g * 8);
        CP16(dst + 16384, srcL + (size_t)r * DDIM + g * 8);
    }
}

__global__ void __launch_bounds__(256) vq_step_mma(const float* __restrict__ books,
                                                   const int* __restrict__ nbu,
                                                   int book) {
    if (book >= *nbu) return;
    extern __shared__ char smem[];
    const uint32_t sbase = smem_u32(smem);
    const int tid = threadIdx.x, lane = tid & 31, wid = tid >> 5;
    const int wr = wid & 3, wc = wid >> 2;
    const int gid = lane >> 2, tg = lane & 3;
    const int tok0 = blockIdx.x * 128;

    float* sCn  = (float*)(smem + OFF_CN);
    float* sV1  = (float*)(smem + OFF_V1);
    float* sV2  = (float*)(smem + OFF_V2);
    int*   sI1  = (int*)(smem + OFF_I1);
    int*   sBI  = (int*)(smem + OFF_BI);
    int*   sUnN = (int*)(smem + OFF_UNC);
    int*   sUn  = (int*)(smem + OFF_UNC + 4);
    float* sR   = (float*)(smem + OFF_SR);
    float* sRV  = (float*)(smem + OFF_RV);
    int*   sRI  = (int*)(smem + OFF_RI);

    if (tid == 0) *sUnN = 0;

    // ---- stage A: residual 128 tok x 256 k, split to bf16 hi/lo, swizzled ----
#pragma unroll 4
    for (int u = 0; u < 16; u++) {
        int idx = tid + u * 256;          // 4096 16B-units: 128 rows x 32
        int t = idx >> 5, gg = idx & 31;  // gg = k granule 0..31
        const float4* rr = (const float4*)(g_resid + (size_t)(tok0 + t) * DDIM);
        float4 a = rr[gg * 2], b = rr[gg * 2 + 1];
        uint4 H, L;
        splitpack(a.x, a.y, H.x, L.x);
        splitpack(a.z, a.w, H.y, L.y);
        splitpack(b.x, b.y, H.z, L.z);
        splitpack(b.z, b.w, H.w, L.w);
        int kc = gg >> 3, g = gg & 7;
        uint32_t off = kc * 16384 + t * 128 + ((g ^ (t & 7)) << 4);
        *(uint4*)(smem + OFF_AH + off) = H;
        *(uint4*)(smem + OFF_AL + off) = L;
    }
    __syncthreads();

    const float* cnb = g_cn + book * NEMB;

    // ldmatrix per-lane address components
    const int xsw = lane & 7;
    const int kg  = lane >> 4;
    const int mrowb0 = (wr * 32 +      (lane & 15)) * 128;
    const int mrowb1 = (wr * 32 + 16 + (lane & 15)) * 128;
    int nrowb[4];
#pragma unroll
    for (int nb = 0; nb < 4; nb++) nrowb[nb] = (wc * 64 + nb * 16 + (lane & 15)) * 128;

    float tv1[4], tv2[4];
    int   ti1[4];
#pragma unroll
    for (int s = 0; s < 4; s++) { tv1[s] = NEG_INF; tv2[s] = NEG_INF; ti1[s] = 0; }

    for (int nt = 0; nt < 8; nt++) {
        if (tid < 128) sCn[tid] = cnb[nt * 128 + tid];

        float acc[2][8][4];
#pragma unroll
        for (int mi = 0; mi < 2; mi++)
#pragma unroll
            for (int ni = 0; ni < 8; ni++)
#pragma unroll
                for (int q = 0; q < 4; q++) acc[mi][ni][q] = 0.f;

        copy_b_chunk(sbase, book, nt, 0, 0, tid);
        CP_COMMIT();

        for (int kc = 0; kc < 4; kc++) {
            if (kc < 3) {
                copy_b_chunk(sbase, book, nt, kc + 1, (kc + 1) & 1, tid);
                CP_COMMIT();
                CP_WAIT1();
            } else {
                CP_WAIT0();
            }
            __syncthreads();

            const uint32_t Akc = kc * 16384;
            const uint32_t Bb  = sbase + OFF_B + (kc & 1) * 32768;

#pragma unroll
            for (int ks = 0; ks < 4; ks++) {
                const int gsw = ((ks * 2 + kg) ^ xsw) << 4;
                uint32_t ah[2][4], al[2][4], bh[4][4], bl[4][4];
                LDSM4(ah[0], sbase + OFF_AH + Akc + mrowb0 + gsw);
                LDSM4(ah[1], sbase + OFF_AH + Akc + mrowb1 + gsw);
                LDSM4(al[0], sbase + OFF_AL + Akc + mrowb0 + gsw);
                LDSM4(al[1], sbase + OFF_AL + Akc + mrowb1 + gsw);
#pragma unroll
                for (int nb = 0; nb < 4; nb++) {
                    LDSM4(bh[nb], Bb + nrowb[nb] + gsw);
                    LDSM4(bl[nb], Bb + 16384 + nrowb[nb] + gsw);
                }
#pragma unroll
                for (int mi = 0; mi < 2; mi++)
#pragma unroll
                    for (int nb = 0; nb < 4; nb++)
#pragma unroll
                        for (int h = 0; h < 2; h++) {
                            float* d = acc[mi][nb * 2 + h];
                            uint32_t* A   = mi ? ah[1] : ah[0];
                            uint32_t* Al2 = mi ? al[1] : al[0];
                            MMA_BF16(d, A,   bh[nb][h], bh[nb][h + 2]);
                            MMA_BF16(d, A,   bl[nb][h], bl[nb][h + 2]);
                            MMA_BF16(d, Al2, bh[nb][h], bh[nb][h + 2]);
                        }
            }
            __syncthreads();
        }

        // fold this nt's 64 scores/thread into per-row running top-2
#pragma unroll
        for (int mi = 0; mi < 2; mi++)
#pragma unroll
            for (int h = 0; h < 2; h++) {
                const int slot = mi * 2 + h;
#pragma unroll
                for (int ni = 0; ni < 8; ni++)
#pragma unroll
                    for (int c = 0; c < 2; c++) {
                        const int col = ni * 8 + tg * 2 + c;
                        float s = acc[mi][ni][h * 2 + c] - sCn[wc * 64 + col];
                        int  ii = nt * 128 + wc * 64 + col;
                        if (s > tv1[slot]) { tv2[slot] = tv1[slot]; tv1[slot] = s; ti1[slot] = ii; }
                        else if (s > tv2[slot]) { tv2[slot] = s; }
                    }
            }
        __syncthreads();   // sCn reused next nt
    }

    // reduce top-2 across the 4 lanes of each quad (same rows, different cols)
#pragma unroll
    for (int off = 1; off <= 2; off <<= 1)
#pragma unroll
        for (int s = 0; s < 4; s++) {
            float ov1 = __shfl_xor_sync(0xffffffffu, tv1[s], off);
            float ov2 = __shfl_xor_sync(0xffffffffu, tv2[s], off);
            int   oi1 = __shfl_xor_sync(0xffffffffu, ti1[s], off);
            top2_merge(tv1[s], ti1[s], tv2[s], ov1, oi1, ov2);
        }
    if (tg == 0) {
#pragma unroll
        for (int s = 0; s < 4; s++) {
            int row = wr * 32 + (s >> 1) * 16 + (s & 1) * 8 + gid;
            sV1[row * 2 + wc] = tv1[s];
            sV2[row * 2 + wc] = tv2[s];
            sI1[row * 2 + wc] = ti1[s];
        }
    }
    __syncthreads();

    if (tid < 128) {
        float v1 = sV1[tid * 2], v2 = sV2[tid * 2];
        int   i1 = sI1[tid * 2];
        top2_merge(v1, i1, v2, sV1[tid * 2 + 1], sI1[tid * 2 + 1], sV2[tid * 2 + 1]);
        sBI[tid] = i1;
        if (v1 - v2 <= DELTA) {
            int p = atomicAdd(sUnN, 1);
            sUn[p] = tid;
        }
    }
    __syncthreads();

    // exact fp32 fallback for uncertain tokens (rare)
    const float* ebk = books + (size_t)book * NEMB * DDIM;
    const int nUnc = *sUnN;
    for (int u = 0; u < nUnc; u++) {
        const int tk = sUn[u];
        sR[tid] = g_resid[(size_t)(tok0 + tk) * DDIM + tid];
        __syncthreads();
        float best = NEG_INF; int bi = 0;
        const float4* sR4 = (const float4*)sR;
#pragma unroll
        for (int e4 = 0; e4 < 4; e4++) {
            const int e = tid * 4 + e4;
            const float4* er = (const float4*)(ebk + (size_t)e * DDIM);
            float a = 0.f;
#pragma unroll 8
            for (int k = 0; k < 64; k++) {
                float4 x = sR4[k], y = er[k];
                a = fmaf(x.x, y.x, a); a = fmaf(x.y, y.y, a);
                a = fmaf(x.z, y.z, a); a = fmaf(x.w, y.w, a);
            }
            float s = a - cnb[e];
            if (s > best) { best = s; bi = e; }   // strict > keeps lowest e
        }
        sRV[tid] = best; sRI[tid] = bi;
        __syncthreads();
        if (tid == 0) {
            float bb = sRV[0]; int ii = sRI[0];
            for (int t = 1; t < 256; t++)
                if (sRV[t] > bb) { bb = sRV[t]; ii = sRI[t]; }
            sBI[tk] = ii;
        }
        __syncthreads();
    }

    // residual update in place (exact fp32 codebook rows; L2-resident)
#pragma unroll 4
    for (int u = 0; u < 32; u++) {
        int i = tid + u * 256;
        int t = i >> 6, d4 = i & 63;
        int idx = sBI[t];
        float4 q = ((const float4*)(ebk + (size_t)idx * DDIM))[d4];
        float4* rp = ((float4*)(g_resid + (size_t)(tok0 + t) * DDIM)) + d4;
        float4 r = *rp;
        r.x -= q.x; r.y -= q.y; r.z -= q.z; r.w -= q.w;
        *rp = r;
    }
}

// ---------------------------------------------------------------------------
extern "C" void kernel_launch(void* const* d_in, const int* in_sizes, int n_in,
                              void* d_out, int out_size) {
    const float* z     = (const float*)d_in[0];
    const float* books = (const float*)d_in[1];
    const int*   nbu   = (const int*)d_in[2];
    float*       out   = (float*)d_out;

    cudaFuncSetAttribute(vq_step_mma, cudaFuncAttributeMaxDynamicSharedMemorySize, SMEM_TC);

    dim3 tgrid(TDIM / 32, DDIM / 32, BDIM);
    dim3 tblk(32, 8);

    init_resid<<<tgrid, tblk>>>(z);
    prep_books<<<(NBOOKS * NEMB) / 8, 256>>>(books);
    for (int k = 0; k < NBOOKS; k++)
        vq_step_mma<<<NTOK / 128, 256, SMEM_TC>>>(books, nbu, k);
    write_out<<<tgrid, tblk>>>(z, out);
}

// round 8
// speedup vs baseline: 1.8318x; 1.6102x over previous
#include <cuda_runtime.h>
#include <cuda_bf16.h>
#include <cstdint>

// Problem constants
#define BDIM   16
#define DDIM   256
#define TDIM   4096
#define NTOK   (BDIM * TDIM)   // 65536
#define NEMB   1024
#define NBOOKS 8

#define NEG_INF (-3.0e38f)
#define DELTA   1.0e-3f        // uncertainty margin >> worst-case split error

// Scratch
__device__ float g_resid[NTOK * DDIM];                  // 64 MB residual (N, D)
__device__ float g_cn[NBOOKS * NEMB];                   // 0.5*||e||^2
// Pre-split bf16 codebooks, plain row-major [book][emb][k=256]
__device__ __nv_bfloat16 g_bh[NBOOKS * NEMB * DDIM];    // 4 MB
__device__ __nv_bfloat16 g_bl[NBOOKS * NEMB * DDIM];    // 4 MB

// ---------------------------------------------------------------------------
// helpers
// ---------------------------------------------------------------------------
__device__ __forceinline__ uint32_t smem_u32(const void* p) {
    uint32_t a;
    asm("{ .reg .u64 t; cvta.to.shared.u64 t, %1; cvt.u32.u64 %0, t; }" : "=r"(a) : "l"(p));
    return a;
}

#define LDSM4(r, addr)                                                         \
    asm volatile("ldmatrix.sync.aligned.m8n8.x4.shared.b16 {%0,%1,%2,%3}, [%4];" \
        : "=r"((r)[0]), "=r"((r)[1]), "=r"((r)[2]), "=r"((r)[3]) : "r"(addr))

#define MMA_BF16(d, a, b0, b1)                                                 \
    asm volatile("mma.sync.aligned.m16n8k16.row.col.f32.bf16.bf16.f32 "        \
        "{%0,%1,%2,%3}, {%4,%5,%6,%7}, {%8,%9}, {%0,%1,%2,%3};"                \
        : "+f"((d)[0]), "+f"((d)[1]), "+f"((d)[2]), "+f"((d)[3])               \
        : "r"((a)[0]), "r"((a)[1]), "r"((a)[2]), "r"((a)[3]), "r"(b0), "r"(b1))

#define CP16(dst, src) asm volatile("cp.async.cg.shared.global [%0], [%1], 16;" :: "r"(dst), "l"(src))
#define CP_COMMIT()    asm volatile("cp.async.commit_group;" ::: "memory")
#define CP_WAIT1()     asm volatile("cp.async.wait_group 1;" ::: "memory")
#define CP_WAIT0()     asm volatile("cp.async.wait_group 0;" ::: "memory")

// bf16 hi/lo split of a float pair, packed low-first (consecutive k)
__device__ __forceinline__ void splitpack(float a, float b, uint32_t& hi, uint32_t& lo) {
    __nv_bfloat16 ah = __float2bfloat16(a), bh = __float2bfloat16(b);
    __nv_bfloat16 al = __float2bfloat16(a - __bfloat162float(ah));
    __nv_bfloat16 bl = __float2bfloat16(b - __bfloat162float(bh));
    __nv_bfloat162 h2; h2.x = ah; h2.y = bh;
    __nv_bfloat162 l2; l2.x = al; l2.y = bl;
    hi = *reinterpret_cast<uint32_t*>(&h2);
    lo = *reinterpret_cast<uint32_t*>(&l2);
}

__device__ __forceinline__ void top2_merge(float& v1, int& i1, float& v2,
                                           float ov1, int oi1, float ov2) {
    if (ov1 > v1) { v2 = fmaxf(v1, ov2); v1 = ov1; i1 = oi1; }
    else          { v2 = fmaxf(v2, ov1); }
}

// ---------------------------------------------------------------------------
// transpose init / finish kernels (proven)
// ---------------------------------------------------------------------------
__global__ void init_resid(const float* __restrict__ z) {
    __shared__ float tile[32][33];
    const int b = blockIdx.z, d0 = blockIdx.y * 32, t0 = blockIdx.x * 32;
    const int tx = threadIdx.x, ty = threadIdx.y;
#pragma unroll
    for (int j = 0; j < 32; j += 8)
        tile[ty + j][tx] = z[(b * DDIM + d0 + ty + j) * TDIM + t0 + tx];
    __syncthreads();
#pragma unroll
    for (int j = 0; j < 32; j += 8)
        g_resid[(b * TDIM + t0 + ty + j) * DDIM + d0 + tx] = tile[tx][ty + j];
}

__global__ void write_out(const float* __restrict__ z, float* __restrict__ out) {
    __shared__ float tile[32][33];
    const int b = blockIdx.z, d0 = blockIdx.y * 32, t0 = blockIdx.x * 32;
    const int tx = threadIdx.x, ty = threadIdx.y;
#pragma unroll
    for (int j = 0; j < 32; j += 8)
        tile[ty + j][tx] = g_resid[(b * TDIM + t0 + ty + j) * DDIM + d0 + tx];
    __syncthreads();
#pragma unroll
    for (int j = 0; j < 32; j += 8) {
        int zi = (b * DDIM + d0 + ty + j) * TDIM + t0 + tx;
        out[zi] = z[zi] - tile[tx][ty + j];
    }
}

// per-embedding half squared norms + bf16 hi/lo split (1 warp = 1 embed row)
__global__ void prep_books(const float* __restrict__ books) {
    const int row  = blockIdx.x * 8 + (threadIdx.x >> 5);   // 0..8191
    const int lane = threadIdx.x & 31;
    const float4* er4 = (const float4*)(books + (size_t)row * DDIM);
    float4 v0 = er4[lane * 2];
    float4 v1 = er4[lane * 2 + 1];
    float s = v0.x*v0.x + v0.y*v0.y + v0.z*v0.z + v0.w*v0.w
            + v1.x*v1.x + v1.y*v1.y + v1.z*v1.z + v1.w*v1.w;
#pragma unroll
    for (int off = 16; off; off >>= 1) s += __shfl_xor_sync(0xffffffffu, s, off);
    if (lane == 0) g_cn[row] = 0.5f * s;

    uint4 H, L;
    splitpack(v0.x, v0.y, H.x, L.x);
    splitpack(v0.z, v0.w, H.y, L.y);
    splitpack(v1.x, v1.y, H.z, L.z);
    splitpack(v1.z, v1.w, H.w, L.w);
    *(uint4*)(g_bh + (size_t)row * DDIM + lane * 8) = H;
    *(uint4*)(g_bl + (size_t)row * DDIM + lane * 8) = L;
}

// ---------------------------------------------------------------------------
// Fused VQ step on mma.sync (HMMA): 3-term bf16-split GEMM + argmax + fallback
// 512 threads = 16 warps (4 token-rows x 4 embed-cols). CTA: 128 tok x 128 emb.
// ---------------------------------------------------------------------------
// smem byte layout.  A: 4 k-chunks of [128 rows][8 x 16B granules, swizzled]
#define OFF_AH   0                 // 64 KB
#define OFF_AL   65536             // 64 KB
#define OFF_B    131072            // 2 bufs x (hi 16KB + lo 16KB)
#define OFF_CN   196608            // 128 f
#define OFF_V1   197120            // 512 f
#define OFF_V2   199168            // 512 f
#define OFF_I1   201216            // 512 i
#define OFF_BI   203264            // 128 i
#define OFF_UNC  203776            // 4 + 128 i
#define OFF_SR   204800            // 256 f
#define OFF_RV   205824            // 512 f
#define OFF_RI   207872            // 512 i
#define SMEM_TC  209920

#define NTHREADS 512

__device__ __forceinline__ void copy_b_chunk(uint32_t sbase, int book, int nt,
                                             int kc, int buf, int tid) {
    const __nv_bfloat16* srcH = g_bh + ((size_t)(book * NEMB + nt * 128) * DDIM + kc * 64);
    const __nv_bfloat16* srcL = g_bl + ((size_t)(book * NEMB + nt * 128) * DDIM + kc * 64);
#pragma unroll
    for (int u = 0; u < 2; u++) {
        int idx = tid + u * NTHREADS;     // 1024 granules: 128 rows x 8
        int r = idx >> 3, g = idx & 7;
        uint32_t dst = sbase + OFF_B + buf * 32768 + r * 128 + ((g ^ (r & 7)) << 4);
        CP16(dst,         srcH + (size_t)r * DDIM + g * 8);
        CP16(dst + 16384, srcL + (size_t)r * DDIM + g * 8);
    }
}

__global__ void __launch_bounds__(NTHREADS) vq_step_mma(const float* __restrict__ books,
                                                        const int* __restrict__ nbu,
                                                        int book) {
    if (book >= *nbu) return;
    extern __shared__ char smem[];
    const uint32_t sbase = smem_u32(smem);
    const int tid = threadIdx.x, lane = tid & 31, wid = tid >> 5;
    const int wr = wid & 3, wc = wid >> 2;           // 4 x 4 warp grid
    const int gid = lane >> 2, tg = lane & 3;
    const int tok0 = blockIdx.x * 128;

    float* sCn  = (float*)(smem + OFF_CN);
    float* sV1  = (float*)(smem + OFF_V1);
    float* sV2  = (float*)(smem + OFF_V2);
    int*   sI1  = (int*)(smem + OFF_I1);
    int*   sBI  = (int*)(smem + OFF_BI);
    int*   sUnN = (int*)(smem + OFF_UNC);
    int*   sUn  = (int*)(smem + OFF_UNC + 4);
    float* sR   = (float*)(smem + OFF_SR);
    float* sRV  = (float*)(smem + OFF_RV);
    int*   sRI  = (int*)(smem + OFF_RI);

    if (tid == 0) *sUnN = 0;

    // ---- stage A: residual 128 tok x 256 k, split to bf16 hi/lo, swizzled ----
#pragma unroll 4
    for (int u = 0; u < 8; u++) {
        int idx = tid + u * NTHREADS;     // 4096 16B-units: 128 rows x 32
        int t = idx >> 5, gg = idx & 31;  // gg = k granule 0..31
        const float4* rr = (const float4*)(g_resid + (size_t)(tok0 + t) * DDIM);
        float4 a = rr[gg * 2], b = rr[gg * 2 + 1];
        uint4 H, L;
        splitpack(a.x, a.y, H.x, L.x);
        splitpack(a.z, a.w, H.y, L.y);
        splitpack(b.x, b.y, H.z, L.z);
        splitpack(b.z, b.w, H.w, L.w);
        int kc = gg >> 3, g = gg & 7;
        uint32_t off = kc * 16384 + t * 128 + ((g ^ (t & 7)) << 4);
        *(uint4*)(smem + OFF_AH + off) = H;
        *(uint4*)(smem + OFF_AL + off) = L;
    }
    __syncthreads();

    const float* cnb = g_cn + book * NEMB;

    // ldmatrix per-lane address components
    const int xsw = lane & 7;
    const int kg  = lane >> 4;
    const int mrowb0 = (wr * 32 +      (lane & 15)) * 128;
    const int mrowb1 = (wr * 32 + 16 + (lane & 15)) * 128;
    int nrowb[2];
#pragma unroll
    for (int nb = 0; nb < 2; nb++) nrowb[nb] = (wc * 32 + nb * 16 + (lane & 15)) * 128;

    float tv1[4], tv2[4];
    int   ti1[4];
#pragma unroll
    for (int s = 0; s < 4; s++) { tv1[s] = NEG_INF; tv2[s] = NEG_INF; ti1[s] = 0; }

    for (int nt = 0; nt < 8; nt++) {
        if (tid < 128) sCn[tid] = cnb[nt * 128 + tid];

        float acc[2][4][4];
#pragma unroll
        for (int mi = 0; mi < 2; mi++)
#pragma unroll
            for (int ni = 0; ni < 4; ni++)
#pragma unroll
                for (int q = 0; q < 4; q++) acc[mi][ni][q] = 0.f;

        copy_b_chunk(sbase, book, nt, 0, 0, tid);
        CP_COMMIT();

        for (int kc = 0; kc < 4; kc++) {
            if (kc < 3) {
                copy_b_chunk(sbase, book, nt, kc + 1, (kc + 1) & 1, tid);
                CP_COMMIT();
                CP_WAIT1();
            } else {
                CP_WAIT0();
            }
            __syncthreads();

            const uint32_t Akc = kc * 16384;
            const uint32_t Bb  = sbase + OFF_B + (kc & 1) * 32768;

#pragma unroll
            for (int ks = 0; ks < 4; ks++) {
                const int gsw = ((ks * 2 + kg) ^ xsw) << 4;
                uint32_t ah[2][4], al[2][4], bh[2][4], bl[2][4];
                LDSM4(ah[0], sbase + OFF_AH + Akc + mrowb0 + gsw);
                LDSM4(ah[1], sbase + OFF_AH + Akc + mrowb1 + gsw);
                LDSM4(al[0], sbase + OFF_AL + Akc + mrowb0 + gsw);
                LDSM4(al[1], sbase + OFF_AL + Akc + mrowb1 + gsw);
#pragma unroll
                for (int nb = 0; nb < 2; nb++) {
                    LDSM4(bh[nb], Bb + nrowb[nb] + gsw);
                    LDSM4(bl[nb], Bb + 16384 + nrowb[nb] + gsw);
                }
#pragma unroll
                for (int mi = 0; mi < 2; mi++)
#pragma unroll
                    for (int nb = 0; nb < 2; nb++)
#pragma unroll
                        for (int h = 0; h < 2; h++) {
                            float* d = acc[mi][nb * 2 + h];
                            uint32_t* A   = mi ? ah[1] : ah[0];
                            uint32_t* Al2 = mi ? al[1] : al[0];
                            MMA_BF16(d, A,   bh[nb][h], bh[nb][h + 2]);
                            MMA_BF16(d, A,   bl[nb][h], bl[nb][h + 2]);
                            MMA_BF16(d, Al2, bh[nb][h], bh[nb][h + 2]);
                        }
            }
            __syncthreads();
        }

        // fold this nt's 32 scores/thread into per-row running top-2
#pragma unroll
        for (int mi = 0; mi < 2; mi++)
#pragma unroll
            for (int h = 0; h < 2; h++) {
                const int slot = mi * 2 + h;
#pragma unroll
                for (int ni = 0; ni < 4; ni++)
#pragma unroll
                    for (int c = 0; c < 2; c++) {
                        const int col = ni * 8 + tg * 2 + c;
                        float s = acc[mi][ni][h * 2 + c] - sCn[wc * 32 + col];
                        int  ii = nt * 128 + wc * 32 + col;
                        if (s > tv1[slot]) { tv2[slot] = tv1[slot]; tv1[slot] = s; ti1[slot] = ii; }
                        else if (s > tv2[slot]) { tv2[slot] = s; }
                    }
            }
        __syncthreads();   // sCn reused next nt
    }

    // reduce top-2 across the 4 lanes of each quad (same rows, different cols)
#pragma unroll
    for (int off = 1; off <= 2; off <<= 1)
#pragma unroll
        for (int s = 0; s < 4; s++) {
            float ov1 = __shfl_xor_sync(0xffffffffu, tv1[s], off);
            float ov2 = __shfl_xor_sync(0xffffffffu, tv2[s], off);
            int   oi1 = __shfl_xor_sync(0xffffffffu, ti1[s], off);
            top2_merge(tv1[s], ti1[s], tv2[s], ov1, oi1, ov2);
        }
    if (tg == 0) {
#pragma unroll
        for (int s = 0; s < 4; s++) {
            int row = wr * 32 + (s >> 1) * 16 + (s & 1) * 8 + gid;
            sV1[row * 4 + wc] = tv1[s];
            sV2[row * 4 + wc] = tv2[s];
            sI1[row * 4 + wc] = ti1[s];
        }
    }
    __syncthreads();

    if (tid < 128) {
        float v1 = sV1[tid * 4], v2 = sV2[tid * 4];
        int   i1 = sI1[tid * 4];
#pragma unroll
        for (int w = 1; w < 4; w++)
            top2_merge(v1, i1, v2, sV1[tid * 4 + w], sI1[tid * 4 + w], sV2[tid * 4 + w]);
        sBI[tid] = i1;
        if (v1 - v2 <= DELTA) {
            int p = atomicAdd(sUnN, 1);
            sUn[p] = tid;
        }
    }
    __syncthreads();

    // exact fp32 fallback for uncertain tokens (rare)
    const float* ebk = books + (size_t)book * NEMB * DDIM;
    const int nUnc = *sUnN;
    for (int u = 0; u < nUnc; u++) {
        const int tk = sUn[u];
        if (tid < 256) sR[tid] = g_resid[(size_t)(tok0 + tk) * DDIM + tid];
        __syncthreads();
        float best = NEG_INF; int bi = 0;
        const float4* sR4 = (const float4*)sR;
#pragma unroll
        for (int e2 = 0; e2 < 2; e2++) {
            const int e = tid * 2 + e2;
            const float4* er = (const float4*)(ebk + (size_t)e * DDIM);
            float a = 0.f;
#pragma unroll 8
            for (int k = 0; k < 64; k++) {
                float4 x = sR4[k], y = er[k];
                a = fmaf(x.x, y.x, a); a = fmaf(x.y, y.y, a);
                a = fmaf(x.z, y.z, a); a = fmaf(x.w, y.w, a);
            }
            float s = a - cnb[e];
            if (s > best) { best = s; bi = e; }   // strict > keeps lowest e
        }
        sRV[tid] = best; sRI[tid] = bi;
        __syncthreads();
        if (tid == 0) {
            float bb = sRV[0]; int ii = sRI[0];
            for (int t = 1; t < NTHREADS; t++)
                if (sRV[t] > bb) { bb = sRV[t]; ii = sRI[t]; }
            sBI[tk] = ii;
        }
        __syncthreads();
    }

    // residual update in place (exact fp32 codebook rows; L2-resident)
#pragma unroll 4
    for (int u = 0; u < 16; u++) {
        int i = tid + u * NTHREADS;
        int t = i >> 6, d4 = i & 63;
        int idx = sBI[t];
        float4 q = ((const float4*)(ebk + (size_t)idx * DDIM))[d4];
        float4* rp = ((float4*)(g_resid + (size_t)(tok0 + t) * DDIM)) + d4;
        float4 r = *rp;
        r.x -= q.x; r.y -= q.y; r.z -= q.z; r.w -= q.w;
        *rp = r;
    }
}

// ---------------------------------------------------------------------------
extern "C" void kernel_launch(void* const* d_in, const int* in_sizes, int n_in,
                              void* d_out, int out_size) {
    const float* z     = (const float*)d_in[0];
    const float* books = (const float*)d_in[1];
    const int*   nbu   = (const int*)d_in[2];
    float*       out   = (float*)d_out;

    cudaFuncSetAttribute(vq_step_mma, cudaFuncAttributeMaxDynamicSharedMemorySize, SMEM_TC);

    dim3 tgrid(TDIM / 32, DDIM / 32, BDIM);
    dim3 tblk(32, 8);

    init_resid<<<tgrid, tblk>>>(z);
    prep_books<<<(NBOOKS * NEMB) / 8, 256>>>(books);
    for (int k = 0; k < NBOOKS; k++)
        vq_step_mma<<<NTOK / 128, NTHREADS, SMEM_TC>>>(books, nbu, k);
    write_out<<<tgrid, tblk>>>(z, out);
}